// round 1
// baseline (speedup 1.0000x reference)
#include <cuda_runtime.h>

// Problem constants
#define BB 8
#define NN 2048
#define FF 256

static __device__ __constant__ const float kNegInf = -1e9f;
#define SLOPE 0.2f

// Scratch (allocation-free rule: __device__ globals)
__device__ float g_h[BB * NN * FF];      // 16.8 MB
__device__ float g_ssrc[BB * NN];
__device__ float g_sdst[BB * NN];

// ---------------------------------------------------------------------------
// Kernel A: h[b,n,o] = sum_f x[b,n,f] * W[o,f]
// Block: 64 rows (flattened b*n) x 64 cols (o). 256 threads, 4x4 micro-tile.
// ---------------------------------------------------------------------------
__global__ __launch_bounds__(256) void gemm_h_kernel(const float* __restrict__ x,
                                                     const float* __restrict__ W) {
    __shared__ float xs[64][33];
    __shared__ float ws[64][33];
    int t = threadIdx.x;
    int tx = t & 15, ty = t >> 4;
    int row0 = blockIdx.x * 64;   // over B*N
    int o0 = blockIdx.y * 64;

    float acc[4][4] = {};

    for (int kt = 0; kt < FF; kt += 32) {
        #pragma unroll
        for (int l = 0; l < 8; l++) {
            int e = t + 256 * l;
            int r = e >> 5, k = e & 31;
            xs[r][k] = x[(size_t)(row0 + r) * FF + kt + k];
            ws[r][k] = W[(size_t)(o0 + r) * FF + kt + k];
        }
        __syncthreads();
        #pragma unroll 8
        for (int k = 0; k < 32; k++) {
            float a[4], bv[4];
            #pragma unroll
            for (int q = 0; q < 4; q++) a[q] = xs[ty * 4 + q][k];
            #pragma unroll
            for (int p = 0; p < 4; p++) bv[p] = ws[tx * 4 + p][k];
            #pragma unroll
            for (int q = 0; q < 4; q++)
                #pragma unroll
                for (int p = 0; p < 4; p++) acc[q][p] += a[q] * bv[p];
        }
        __syncthreads();
    }
    #pragma unroll
    for (int q = 0; q < 4; q++)
        #pragma unroll
        for (int p = 0; p < 4; p++)
            g_h[(size_t)(row0 + ty * 4 + q) * FF + o0 + tx * 4 + p] = acc[q][p];
}

// ---------------------------------------------------------------------------
// Kernel S: s_src[r] = h[r,:].a_src ; s_dst[r] = h[r,:].a_dst  (warp per row)
// ---------------------------------------------------------------------------
__global__ __launch_bounds__(256) void score_kernel(const float* __restrict__ a_src,
                                                    const float* __restrict__ a_dst) {
    __shared__ float as[FF], ad[FF];
    int t = threadIdx.x;
    as[t] = a_src[t];
    ad[t] = a_dst[t];
    __syncthreads();
    int warp = t >> 5, lane = t & 31;
    int row = blockIdx.x * 8 + warp;
    const float* hr = &g_h[(size_t)row * FF];
    float s1 = 0.f, s2 = 0.f;
    #pragma unroll
    for (int c = lane; c < FF; c += 32) {
        float hv = hr[c];
        s1 += hv * as[c];
        s2 += hv * ad[c];
    }
    #pragma unroll
    for (int o = 16; o; o >>= 1) {
        s1 += __shfl_xor_sync(0xFFFFFFFFu, s1, o);
        s2 += __shfl_xor_sync(0xFFFFFFFFu, s2, o);
    }
    if (lane == 0) { g_ssrc[row] = s1; g_sdst[row] = s2; }
}

// ---------------------------------------------------------------------------
// Kernel B: fused masked-softmax + alpha @ h. Block = (b, 64-row i-tile).
// Phase 1: per-row max + sum(exp) (two sub-passes over adj row, L1-hot reread).
// Phase 2: stream 64-wide j chunks; p tile in smem; 8x8 register GEMM; scale
//          by 1/d only in epilogue.
// ---------------------------------------------------------------------------
struct SmemB {
    float sdst[NN];        // 8 KB  (full s_dst row for this batch)
    float ssrc[64];
    float m[64];
    float invd[64];
    float h[64][FF];       // 64 KB
    float p[64][68];       // 17 KB (transposed [j][i], padded for banks/align)
};

__global__ __launch_bounds__(256, 2) void attn_kernel(const int* __restrict__ adj,
                                                      float* __restrict__ out) {
    extern __shared__ char smem_raw[];
    SmemB* sm = reinterpret_cast<SmemB*>(smem_raw);

    int t = threadIdx.x;
    int b = blockIdx.y;
    int i0 = blockIdx.x * 64;

    for (int c = t; c < NN; c += 256) sm->sdst[c] = g_sdst[b * NN + c];
    if (t < 64) sm->ssrc[t] = g_ssrc[b * NN + i0 + t];
    __syncthreads();

    // ---------------- Phase 1: row max + denominator -----------------------
    {
        int warp = t >> 5, lane = t & 31;
        const float4* sd4 = reinterpret_cast<const float4*>(sm->sdst);
        for (int rr = 0; rr < 8; rr++) {
            int i = warp * 8 + rr;
            float sv = sm->ssrc[i];
            const int4* ar = reinterpret_cast<const int4*>(
                adj + ((size_t)b * NN + i0 + i) * NN);

            // pass a: masked max
            float ml = kNegInf;
            for (int stp = 0; stp < 16; stp++) {
                int4 av = ar[lane + 32 * stp];
                float4 dv = sd4[lane + 32 * stp];
                float e0 = sv + dv.x; e0 = e0 > 0.f ? e0 : SLOPE * e0;
                float e1 = sv + dv.y; e1 = e1 > 0.f ? e1 : SLOPE * e1;
                float e2 = sv + dv.z; e2 = e2 > 0.f ? e2 : SLOPE * e2;
                float e3 = sv + dv.w; e3 = e3 > 0.f ? e3 : SLOPE * e3;
                if (av.x == 0) e0 = kNegInf;
                if (av.y == 0) e1 = kNegInf;
                if (av.z == 0) e2 = kNegInf;
                if (av.w == 0) e3 = kNegInf;
                ml = fmaxf(ml, fmaxf(fmaxf(e0, e1), fmaxf(e2, e3)));
            }
            #pragma unroll
            for (int o = 16; o; o >>= 1)
                ml = fmaxf(ml, __shfl_xor_sync(0xFFFFFFFFu, ml, o));

            // pass b: sum exp (adj reread is L1-hot)
            float dl = 0.f;
            for (int stp = 0; stp < 16; stp++) {
                int4 av = ar[lane + 32 * stp];
                float4 dv = sd4[lane + 32 * stp];
                float e0 = sv + dv.x; e0 = e0 > 0.f ? e0 : SLOPE * e0;
                float e1 = sv + dv.y; e1 = e1 > 0.f ? e1 : SLOPE * e1;
                float e2 = sv + dv.z; e2 = e2 > 0.f ? e2 : SLOPE * e2;
                float e3 = sv + dv.w; e3 = e3 > 0.f ? e3 : SLOPE * e3;
                if (av.x == 0) e0 = kNegInf;
                if (av.y == 0) e1 = kNegInf;
                if (av.z == 0) e2 = kNegInf;
                if (av.w == 0) e3 = kNegInf;
                dl += __expf(e0 - ml) + __expf(e1 - ml) +
                      __expf(e2 - ml) + __expf(e3 - ml);
            }
            #pragma unroll
            for (int o = 16; o; o >>= 1)
                dl += __shfl_xor_sync(0xFFFFFFFFu, dl, o);

            if (lane == 0) {
                sm->m[i] = ml;
                sm->invd[i] = (dl > 0.f) ? (1.f / dl) : 0.f;
            }
        }
    }
    __syncthreads();

    // ---------------- Phase 2: out = (p @ h_tile) * invd -------------------
    float acc[8][8] = {};
    int ty = t >> 5, tx = t & 31;   // ty: 8 i-groups, tx: 32 f-groups

    for (int jc = 0; jc < NN; jc += 64) {
        __syncthreads();  // protect previous p/h tiles

        // load h tile (64 x 256 floats) via float4
        const float4* hsrc = reinterpret_cast<const float4*>(
            &g_h[((size_t)b * NN + jc) * FF]);
        #pragma unroll
        for (int l = 0; l < 16; l++) {
            int e = t + 256 * l;
            int j = e >> 6, f4 = e & 63;
            reinterpret_cast<float4*>(&sm->h[j][0])[f4] = hsrc[j * 64 + f4];
        }

        // compute p tile (transposed, [j][i])
        {
            int jl = t & 63, isub = t >> 6;  // 0..3
            #pragma unroll
            for (int r = 0; r < 16; r++) {
                int i = isub + r * 4;
                int a = adj[((size_t)b * NN + i0 + i) * NN + jc + jl];
                float e = sm->ssrc[i] + sm->sdst[jc + jl];
                e = e > 0.f ? e : SLOPE * e;
                float pv = (a != 0) ? __expf(e - sm->m[i]) : 0.f;
                sm->p[jl][i] = pv;
            }
        }
        __syncthreads();

        #pragma unroll 4
        for (int kk = 0; kk < 64; kk++) {
            float4 p0 = *reinterpret_cast<const float4*>(&sm->p[kk][ty * 8]);
            float4 p1 = *reinterpret_cast<const float4*>(&sm->p[kk][ty * 8 + 4]);
            float4 h0 = *reinterpret_cast<const float4*>(&sm->h[kk][tx * 8]);
            float4 h1 = *reinterpret_cast<const float4*>(&sm->h[kk][tx * 8 + 4]);
            float pa[8] = {p0.x, p0.y, p0.z, p0.w, p1.x, p1.y, p1.z, p1.w};
            float hb[8] = {h0.x, h0.y, h0.z, h0.w, h1.x, h1.y, h1.z, h1.w};
            #pragma unroll
            for (int q = 0; q < 8; q++)
                #pragma unroll
                for (int p = 0; p < 8; p++)
                    acc[q][p] += pa[q] * hb[p];
        }
    }

    // epilogue: scale by 1/d, write out
    #pragma unroll
    for (int q = 0; q < 8; q++) {
        int i = ty * 8 + q;
        float sc = sm->invd[i];
        float* orow = out + ((size_t)b * NN + i0 + i) * FF + tx * 8;
        float4 v0 = make_float4(acc[q][0] * sc, acc[q][1] * sc,
                                acc[q][2] * sc, acc[q][3] * sc);
        float4 v1 = make_float4(acc[q][4] * sc, acc[q][5] * sc,
                                acc[q][6] * sc, acc[q][7] * sc);
        reinterpret_cast<float4*>(orow)[0] = v0;
        reinterpret_cast<float4*>(orow)[1] = v1;
    }
}

// ---------------------------------------------------------------------------
extern "C" void kernel_launch(void* const* d_in, const int* in_sizes, int n_in,
                              void* d_out, int out_size) {
    const float* x     = (const float*)d_in[0];  // (B,N,F_in)
    const int*   adj   = (const int*)d_in[1];    // (B,N,N)
    const float* W     = (const float*)d_in[2];  // (F_out,F_in)
    const float* a_src = (const float*)d_in[3];  // (F_out)
    const float* a_dst = (const float*)d_in[4];  // (F_out)
    float* out = (float*)d_out;                  // (B,N,F_out)

    (void)in_sizes; (void)n_in; (void)out_size;

    // h = x @ W^T
    gemm_h_kernel<<<dim3((BB * NN) / 64, FF / 64), 256>>>(x, W);
    // s_src, s_dst
    score_kernel<<<(BB * NN) / 8, 256>>>(a_src, a_dst);
    // fused masked softmax + alpha @ h
    cudaFuncSetAttribute(attn_kernel, cudaFuncAttributeMaxDynamicSharedMemorySize,
                         (int)sizeof(SmemB));
    attn_kernel<<<dim3(NN / 64, BB), 256, sizeof(SmemB)>>>(adj, out);
}

// round 2
// speedup vs baseline: 2.1789x; 2.1789x over previous
#include <cuda_runtime.h>
#include <cstdint>

// Problem constants
#define BB 8
#define NN 2048
#define FF 256
#define SLOPE 0.2f

// Scratch (allocation-free rule: __device__ globals)
__device__ float g_h[BB * NN * FF];      // 16.8 MB
__device__ float g_ssrc[BB * NN];
__device__ float g_sdst[BB * NN];

// ---------------------------------------------------------------------------
// Kernel A: h[b,n,o] = sum_f x[b,n,f] * W[o,f]   (fp32, unchanged this round)
// ---------------------------------------------------------------------------
__global__ __launch_bounds__(256) void gemm_h_kernel(const float* __restrict__ x,
                                                     const float* __restrict__ W) {
    __shared__ float xs[64][33];
    __shared__ float ws[64][33];
    int t = threadIdx.x;
    int tx = t & 15, ty = t >> 4;
    int row0 = blockIdx.x * 64;   // over B*N
    int o0 = blockIdx.y * 64;

    float acc[4][4] = {};

    for (int kt = 0; kt < FF; kt += 32) {
        #pragma unroll
        for (int l = 0; l < 8; l++) {
            int e = t + 256 * l;
            int r = e >> 5, k = e & 31;
            xs[r][k] = x[(size_t)(row0 + r) * FF + kt + k];
            ws[r][k] = W[(size_t)(o0 + r) * FF + kt + k];
        }
        __syncthreads();
        #pragma unroll 8
        for (int k = 0; k < 32; k++) {
            float a[4], bv[4];
            #pragma unroll
            for (int q = 0; q < 4; q++) a[q] = xs[ty * 4 + q][k];
            #pragma unroll
            for (int p = 0; p < 4; p++) bv[p] = ws[tx * 4 + p][k];
            #pragma unroll
            for (int q = 0; q < 4; q++)
                #pragma unroll
                for (int p = 0; p < 4; p++) acc[q][p] += a[q] * bv[p];
        }
        __syncthreads();
    }
    #pragma unroll
    for (int q = 0; q < 4; q++)
        #pragma unroll
        for (int p = 0; p < 4; p++)
            g_h[(size_t)(row0 + ty * 4 + q) * FF + o0 + tx * 4 + p] = acc[q][p];
}

// ---------------------------------------------------------------------------
// Kernel S: s_src[r] = h[r,:].a_src ; s_dst[r] = h[r,:].a_dst  (warp per row)
// ---------------------------------------------------------------------------
__global__ __launch_bounds__(256) void score_kernel(const float* __restrict__ a_src,
                                                    const float* __restrict__ a_dst) {
    __shared__ float as[FF], ad[FF];
    int t = threadIdx.x;
    as[t] = a_src[t];
    ad[t] = a_dst[t];
    __syncthreads();
    int warp = t >> 5, lane = t & 31;
    int row = blockIdx.x * 8 + warp;
    const float* hr = &g_h[(size_t)row * FF];
    float s1 = 0.f, s2 = 0.f;
    #pragma unroll
    for (int c = lane; c < FF; c += 32) {
        float hv = hr[c];
        s1 += hv * as[c];
        s2 += hv * ad[c];
    }
    #pragma unroll
    for (int o = 16; o; o >>= 1) {
        s1 += __shfl_xor_sync(0xFFFFFFFFu, s1, o);
        s2 += __shfl_xor_sync(0xFFFFFFFFu, s2, o);
    }
    if (lane == 0) { g_ssrc[row] = s1; g_sdst[row] = s2; }
}

// ---------------------------------------------------------------------------
// Kernel B: fused masked-softmax (no max pass; e is bounded) + alpha @ h via
// tf32 mma.sync tensor cores. Block = (b, 64-row i-tile), 256 threads.
// Warps: 2 (i) x 4 (f); each warp owns m32 x n64 of the 64x256 output tile.
// ---------------------------------------------------------------------------
#define HS 264   // h tile row stride in words (256 + 8 pad -> conflict-free B LDS)
#define PS 68    // p tile row stride in words (64 + 4 pad  -> conflict-free LDSM)

struct SmemB {
    float sdst[NN];        // 8 KB
    float ssrc[64];
    float invd[64];
    float h[64 * HS];      // 67584 B  (tf32-rounded h tile, [j][f])
    float p[64 * PS];      // 17408 B  (tf32-rounded p tile, [i][j])
};                          // total ~93.7 KB -> 2 CTAs/SM

__device__ __forceinline__ uint32_t tf32r(float f) {
    uint32_t u;
    asm("cvt.rna.tf32.f32 %0, %1;" : "=r"(u) : "f"(f));
    return u;
}

__device__ __forceinline__ void ldsm_x4(uint32_t* r, uint32_t addr) {
    asm volatile("ldmatrix.sync.aligned.m8n8.x4.shared.b16 {%0,%1,%2,%3}, [%4];"
                 : "=r"(r[0]), "=r"(r[1]), "=r"(r[2]), "=r"(r[3]) : "r"(addr));
}

__device__ __forceinline__ void mma_tf32(float* d, const uint32_t* a,
                                         const uint32_t* b) {
    asm volatile(
        "mma.sync.aligned.m16n8k8.row.col.f32.tf32.tf32.f32 "
        "{%0,%1,%2,%3}, {%4,%5,%6,%7}, {%8,%9}, {%0,%1,%2,%3};"
        : "+f"(d[0]), "+f"(d[1]), "+f"(d[2]), "+f"(d[3])
        : "r"(a[0]), "r"(a[1]), "r"(a[2]), "r"(a[3]), "r"(b[0]), "r"(b[1]));
}

__global__ __launch_bounds__(256, 2) void attn_kernel(const int* __restrict__ adj,
                                                      float* __restrict__ out) {
    extern __shared__ char smem_raw[];
    SmemB* sm = reinterpret_cast<SmemB*>(smem_raw);

    int t = threadIdx.x;
    int b = blockIdx.y;
    int i0 = blockIdx.x * 64;

    for (int c = t; c < NN; c += 256) sm->sdst[c] = g_sdst[b * NN + c];
    if (t < 64) sm->ssrc[t] = g_ssrc[b * NN + i0 + t];

    // p-compute mapping: thread -> (row pi, j sub-block jsub of 16)
    int pi = t >> 2;          // 0..63
    int jsub = t & 3;         // 0..3
    const int* adj_row = adj + ((size_t)b * NN + i0 + pi) * NN;
    float dreg = 0.f;

    // mma mapping
    int warp = t >> 5, lane = t & 31;
    int wr = warp >> 2, wc = warp & 3;      // 2 x 4 warp grid
    int mbase = wr * 32;                     // i offset in tile
    int nbase = wc * 64;                     // f offset in tile
    int lg = lane >> 3;                      // ldmatrix group 0..3
    int lr = lane & 7;
    int lq = lane >> 2;                      // 0..7
    int lc = lane & 3;                       // 0..3

    uint32_t p_u32, h_u32;
    {
        uint64_t tmp;
        asm("cvta.to.shared.u64 %0, %1;" : "=l"(tmp) : "l"((void*)sm->p));
        p_u32 = (uint32_t)tmp;
        asm("cvta.to.shared.u64 %0, %1;" : "=l"(tmp) : "l"((void*)sm->h));
        h_u32 = (uint32_t)tmp;
    }
    // ldmatrix per-lane row address offset (bytes), per m-tile; k0 added in loop
    // g0: row lr, k0 ; g1: row lr+8, k0 ; g2: row lr, k0+4 ; g3: row lr+8, k0+4
    int a_row = lr + ((lg & 1) ? 8 : 0);
    int a_kofs = (lg >= 2) ? 4 : 0;

    float acc[2][8][4] = {};

    __syncthreads();
    float svp = sm->ssrc[pi];

    const float* hsrc_b = &g_h[(size_t)b * NN * FF];

    for (int jc = 0; jc < NN; jc += 64) {
        // ---- fill h tile (tf32-rounded), [j][f] stride HS ----
        const float4* hg = reinterpret_cast<const float4*>(hsrc_b + (size_t)jc * FF);
        #pragma unroll
        for (int l = 0; l < 16; l++) {
            int e = t + 256 * l;
            int j = e >> 6, f4 = e & 63;
            float4 v = hg[j * 64 + f4];
            uint4 u = make_uint4(tf32r(v.x), tf32r(v.y), tf32r(v.z), tf32r(v.w));
            *reinterpret_cast<uint4*>(&sm->h[j * HS + f4 * 4]) = u;
        }
        // ---- compute p tile (tf32-rounded), [i][j] stride PS; accumulate d ----
        {
            const int4* ar = reinterpret_cast<const int4*>(adj_row + jc + jsub * 16);
            #pragma unroll
            for (int q = 0; q < 4; q++) {
                int4 av = ar[q];
                int j = jsub * 16 + q * 4;
                float4 dv = *reinterpret_cast<const float4*>(&sm->sdst[jc + j]);
                float e0 = svp + dv.x; e0 = e0 > 0.f ? e0 : SLOPE * e0;
                float e1 = svp + dv.y; e1 = e1 > 0.f ? e1 : SLOPE * e1;
                float e2 = svp + dv.z; e2 = e2 > 0.f ? e2 : SLOPE * e2;
                float e3 = svp + dv.w; e3 = e3 > 0.f ? e3 : SLOPE * e3;
                float p0 = av.x ? __expf(e0) : 0.f;
                float p1 = av.y ? __expf(e1) : 0.f;
                float p2 = av.z ? __expf(e2) : 0.f;
                float p3 = av.w ? __expf(e3) : 0.f;
                dreg += (p0 + p1) + (p2 + p3);
                uint4 pu = make_uint4(tf32r(p0), tf32r(p1), tf32r(p2), tf32r(p3));
                *reinterpret_cast<uint4*>(&sm->p[pi * PS + j]) = pu;
            }
        }
        __syncthreads();

        // ---- tensor-core GEMM: acc += p[m32 x 64] @ h[64 x n64] ----
        #pragma unroll
        for (int k0 = 0; k0 < 64; k0 += 8) {
            uint32_t afr[2][4];
            #pragma unroll
            for (int mt = 0; mt < 2; mt++) {
                uint32_t addr = p_u32 +
                    (uint32_t)(((mbase + mt * 16 + a_row) * PS + k0 + a_kofs) * 4);
                ldsm_x4(afr[mt], addr);
            }
            uint32_t bfr[8][2];
            #pragma unroll
            for (int nt = 0; nt < 8; nt++) {
                int n = nbase + nt * 8 + lq;
                int kk = k0 + lc;
                bfr[nt][0] = __float_as_uint(sm->h[kk * HS + n]);
                bfr[nt][1] = __float_as_uint(sm->h[(kk + 4) * HS + n]);
            }
            #pragma unroll
            for (int mt = 0; mt < 2; mt++)
                #pragma unroll
                for (int nt = 0; nt < 8; nt++)
                    mma_tf32(acc[mt][nt], afr[mt], bfr[nt]);
        }
        __syncthreads();
    }

    // ---- finalize denominators ----
    dreg += __shfl_xor_sync(0xFFFFFFFFu, dreg, 1);
    dreg += __shfl_xor_sync(0xFFFFFFFFu, dreg, 2);
    if (jsub == 0) sm->invd[pi] = (dreg > 0.f) ? (1.f / dreg) : 0.f;
    __syncthreads();

    // ---- epilogue: scale by 1/d, write out ----
    #pragma unroll
    for (int mt = 0; mt < 2; mt++) {
        int r0 = mbase + mt * 16 + lq;       // rows r0 and r0+8
        float s0 = sm->invd[r0];
        float s1 = sm->invd[r0 + 8];
        float* o0 = out + ((size_t)b * NN + i0 + r0) * FF + nbase;
        float* o1 = o0 + (size_t)8 * FF;
        #pragma unroll
        for (int nt = 0; nt < 8; nt++) {
            int c = nt * 8 + 2 * lc;
            float2 v0 = make_float2(acc[mt][nt][0] * s0, acc[mt][nt][1] * s0);
            float2 v1 = make_float2(acc[mt][nt][2] * s1, acc[mt][nt][3] * s1);
            *reinterpret_cast<float2*>(o0 + c) = v0;
            *reinterpret_cast<float2*>(o1 + c) = v1;
        }
    }
}

// ---------------------------------------------------------------------------
extern "C" void kernel_launch(void* const* d_in, const int* in_sizes, int n_in,
                              void* d_out, int out_size) {
    const float* x     = (const float*)d_in[0];  // (B,N,F_in)
    const int*   adj   = (const int*)d_in[1];    // (B,N,N)
    const float* W     = (const float*)d_in[2];  // (F_out,F_in)
    const float* a_src = (const float*)d_in[3];  // (F_out)
    const float* a_dst = (const float*)d_in[4];  // (F_out)
    float* out = (float*)d_out;                  // (B,N,F_out)

    (void)in_sizes; (void)n_in; (void)out_size;

    // h = x @ W^T
    gemm_h_kernel<<<dim3((BB * NN) / 64, FF / 64), 256>>>(x, W);
    // s_src, s_dst
    score_kernel<<<(BB * NN) / 8, 256>>>(a_src, a_dst);
    // fused masked softmax + alpha @ h (tensor cores)
    cudaFuncSetAttribute(attn_kernel, cudaFuncAttributeMaxDynamicSharedMemorySize,
                         (int)sizeof(SmemB));
    attn_kernel<<<dim3(NN / 64, BB), 256, sizeof(SmemB)>>>(adj, out);
}

// round 5
// speedup vs baseline: 3.9334x; 1.8052x over previous
#include <cuda_runtime.h>
#include <cuda_fp16.h>
#include <cstdint>

// Problem constants
#define BB 8
#define NN 2048
#define FF 256
#define CHUNKS (NN / 64)

// Scratch (allocation-free rule: __device__ globals)
__device__ __half g_xh[BB * NN * FF];    // x in f16              8.4 MB
__device__ __half g_Wh[FF * FF];         // W in f16
__device__ __half g_hTh[BB * FF * NN];   // h f16, [b][f][n]      8.4 MB
__device__ float g_es1[BB * NN];         // exp(s_src)
__device__ float g_es2[BB * NN];         // exp(0.2*s_src)
__device__ float g_ed1[BB * NN];         // exp(s_dst)
__device__ float g_ed2[BB * NN];         // exp(0.2*s_dst)

// ---------------------------------------------------------------------------
// helpers
// ---------------------------------------------------------------------------
__device__ __forceinline__ uint32_t smem_u32(const void* p) {
    uint32_t a;
    asm("{ .reg .u64 t; cvta.to.shared.u64 t, %1; cvt.u32.u64 %0, t; }"
        : "=r"(a) : "l"(p));
    return a;
}

__device__ __forceinline__ void cp16(uint32_t dst, const void* src) {
    asm volatile(
        "{ .reg .u64 g; cvta.to.global.u64 g, %1;"
        "  cp.async.cg.shared.global [%0], [g], 16; }"
        ::"r"(dst), "l"(src) : "memory");
}
#define CP_COMMIT() asm volatile("cp.async.commit_group;" ::: "memory")
#define CP_WAIT1() asm volatile("cp.async.wait_group 1;" ::: "memory")
#define CP_WAIT0() asm volatile("cp.async.wait_group 0;" ::: "memory")

__device__ __forceinline__ void ldsm4(uint32_t* r, uint32_t a) {
    asm volatile("ldmatrix.sync.aligned.m8n8.x4.shared.b16 {%0,%1,%2,%3}, [%4];"
                 : "=r"(r[0]), "=r"(r[1]), "=r"(r[2]), "=r"(r[3]) : "r"(a));
}

__device__ __forceinline__ void mma_f16(float* d, const uint32_t* a, uint32_t b0,
                                        uint32_t b1) {
    asm volatile(
        "mma.sync.aligned.m16n8k16.row.col.f32.f16.f16.f32 "
        "{%0,%1,%2,%3}, {%4,%5,%6,%7}, {%8,%9}, {%0,%1,%2,%3};"
        : "+f"(d[0]), "+f"(d[1]), "+f"(d[2]), "+f"(d[3])
        : "r"(a[0]), "r"(a[1]), "r"(a[2]), "r"(a[3]), "r"(b0), "r"(b1));
}

// tile row stride: 64 f16 + 8 pad = 144 bytes (9 x 16B -> conflict-free LDSM)
#define TSTRIDE 144

// ---------------------------------------------------------------------------
// convert fp32 -> f16: reference device globals DIRECTLY (host cannot pass
// __device__ global addresses as kernel args).
// ---------------------------------------------------------------------------
__global__ __launch_bounds__(256) void cvt_x_kernel(const float4* __restrict__ src) {
    int i = blockIdx.x * 256 + threadIdx.x;   // over BB*NN*FF/4
    float4 v = src[i];
    __half2* dst = reinterpret_cast<__half2*>(g_xh);
    dst[i * 2] = __floats2half2_rn(v.x, v.y);
    dst[i * 2 + 1] = __floats2half2_rn(v.z, v.w);
}
__global__ __launch_bounds__(256) void cvt_w_kernel(const float4* __restrict__ src) {
    int i = blockIdx.x * 256 + threadIdx.x;   // over FF*FF/4
    float4 v = src[i];
    __half2* dst = reinterpret_cast<__half2*>(g_Wh);
    dst[i * 2] = __floats2half2_rn(v.x, v.y);
    dst[i * 2 + 1] = __floats2half2_rn(v.z, v.w);
}

// ---------------------------------------------------------------------------
// gemm_h: h_T[b][f][n] = sum_k W[f][k] * x[b][n][k]   (f16 mma, f32 accum)
// CTA: m128(f) x n128, 256 threads = 8 warps (2m x 4n), warp m64 x n32.
// K=256 in 4 chunks of 64, cp.async double buffered.
// ---------------------------------------------------------------------------
#define GH_SMEM (4 * 128 * TSTRIDE)   // A0,A1,B0,B1 each 128*144
__global__ __launch_bounds__(256, 2) void gemm_h_kernel() {
    extern __shared__ char smraw[];
    uint32_t su = smem_u32(smraw);
    const uint32_t AB[2] = {su, su + 128 * TSTRIDE};
    const uint32_t XB[2] = {su + 2 * 128 * TSTRIDE, su + 3 * 128 * TSTRIDE};

    int t = threadIdx.x, l = t & 31, w = t >> 5;
    int b = blockIdx.z, n0 = blockIdx.x * 128, m0 = blockIdx.y * 128;
    int mbase = (w & 1) * 64, nbase = (w >> 1) * 32;
    int a_row = (l & 7) + ((l & 8) ? 8 : 0);
    int a_k = (l & 16) ? 16 : 0;
    int b_row = (l & 7) + ((l & 16) ? 8 : 0);
    int b_k = (l & 8) ? 16 : 0;

    const __half* Wsrc = g_Wh + (size_t)m0 * FF;
    const __half* Xsrc = g_xh + ((size_t)b * NN + n0) * FF;
    int fr = t >> 1, fs = (t & 1) * 4;  // 2 threads/row, 4 segs each

    float acc[4][4][4] = {};

    #define GH_FILL(kc, s)                                                   \
        do {                                                                 \
            _Pragma("unroll")                                                \
            for (int q = 0; q < 4; q++) {                                    \
                cp16(AB[s] + fr * TSTRIDE + (fs + q) * 16,                   \
                     Wsrc + (size_t)fr * FF + (kc) + (fs + q) * 8);          \
                cp16(XB[s] + fr * TSTRIDE + (fs + q) * 16,                   \
                     Xsrc + (size_t)fr * FF + (kc) + (fs + q) * 8);          \
            }                                                                \
            CP_COMMIT();                                                     \
        } while (0)

    GH_FILL(0, 0);
    for (int c = 0; c < 4; c++) {
        int s = c & 1;
        if (c < 3) GH_FILL((c + 1) * 64, s ^ 1);
        if (c < 3) CP_WAIT1(); else CP_WAIT0();
        __syncthreads();
        #pragma unroll
        for (int kk = 0; kk < 4; kk++) {
            uint32_t bf[2][4];
            #pragma unroll
            for (int g = 0; g < 2; g++)
                ldsm4(bf[g], XB[s] + (nbase + g * 16 + b_row) * TSTRIDE +
                                 kk * 32 + b_k);
            #pragma unroll
            for (int mt = 0; mt < 4; mt++) {
                uint32_t a[4];
                ldsm4(a, AB[s] + (mbase + mt * 16 + a_row) * TSTRIDE +
                             kk * 32 + a_k);
                #pragma unroll
                for (int g = 0; g < 2; g++) {
                    mma_f16(acc[mt][2 * g], a, bf[g][0], bf[g][1]);
                    mma_f16(acc[mt][2 * g + 1], a, bf[g][2], bf[g][3]);
                }
            }
        }
        __syncthreads();
    }

    #pragma unroll
    for (int mt = 0; mt < 4; mt++) {
        int f = m0 + mbase + mt * 16 + (l >> 2);
        #pragma unroll
        for (int nt = 0; nt < 4; nt++) {
            int n = n0 + nbase + nt * 8 + 2 * (l & 3);
            *reinterpret_cast<__half2*>(&g_hTh[((size_t)b * FF + f) * NN + n]) =
                __floats2half2_rn(acc[mt][nt][0], acc[mt][nt][1]);
            *reinterpret_cast<__half2*>(&g_hTh[((size_t)b * FF + f + 8) * NN + n]) =
                __floats2half2_rn(acc[mt][nt][2], acc[mt][nt][3]);
        }
    }
}

// ---------------------------------------------------------------------------
// score: per-node s_src/s_dst dot products -> exp factor arrays
// ---------------------------------------------------------------------------
__global__ __launch_bounds__(256) void score_kernel(const float* __restrict__ a_src,
                                                    const float* __restrict__ a_dst) {
    __shared__ float as[FF], ad[FF];
    int t = threadIdx.x;
    as[t] = a_src[t];
    ad[t] = a_dst[t];
    __syncthreads();
    int g = blockIdx.x * 256 + t;
    int b = g >> 11, n = g & 2047;
    const __half* hb = g_hTh + (size_t)b * FF * NN + n;
    float s1 = 0.f, s2 = 0.f;
    #pragma unroll 8
    for (int f = 0; f < FF; f++) {
        float hv = __half2float(hb[(size_t)f * NN]);
        s1 += hv * as[f];
        s2 += hv * ad[f];
    }
    g_es1[g] = __expf(s1);
    g_es2[g] = __expf(0.2f * s1);
    g_ed1[g] = __expf(s2);
    g_ed2[g] = __expf(0.2f * s2);
}

// ---------------------------------------------------------------------------
// attn: fused masked softmax + alpha @ h, f16 mma.
// CTA = (b, 128-row i-tile). 512 threads = 16 warps (4i x 4n), warp m32 x n64.
// Per 64-j chunk: p tile (128x64 f16, [i][k]) computed in-regs -> smem;
// h tile (256x64 f16, [n][k]) via cp.async double buffer; adj prefetched.
// ---------------------------------------------------------------------------
#define ITILE 128
#define OFF_P0 0
#define OFF_P1 (128 * TSTRIDE)
#define OFF_H0 (2 * 128 * TSTRIDE)                  // 36864
#define OFF_H1 (OFF_H0 + 256 * TSTRIDE)             // 73728
#define OFF_SE (OFF_H1 + 256 * TSTRIDE)             // 110592
#define OFF_SG (OFF_SE + NN * 4)                    // 118784
#define OFF_ES1 (OFF_SG + NN * 4)                   // 126976
#define OFF_ES2 (OFF_ES1 + 512)
#define OFF_INVD (OFF_ES2 + 512)
#define AT_SMEM (OFF_INVD + 512)                    // 128512

__global__ __launch_bounds__(512, 1) void attn_kernel(const int* __restrict__ adj,
                                                      float* __restrict__ out) {
    extern __shared__ char smraw[];
    uint32_t su = smem_u32(smraw);
    float* sE = reinterpret_cast<float*>(smraw + OFF_SE);
    float* sG = reinterpret_cast<float*>(smraw + OFF_SG);
    float* eS1 = reinterpret_cast<float*>(smraw + OFF_ES1);
    float* eS2 = reinterpret_cast<float*>(smraw + OFF_ES2);
    float* invd = reinterpret_cast<float*>(smraw + OFF_INVD);

    int t = threadIdx.x, l = t & 31, w = t >> 5;
    int b = blockIdx.y;
    int i0 = blockIdx.x * ITILE;

    for (int c = t; c < NN; c += 512) {
        sE[c] = g_ed1[b * NN + c];
        sG[c] = g_ed2[b * NN + c];
    }
    if (t < ITILE) {
        eS1[t] = g_es1[b * NN + i0 + t];
        eS2[t] = g_es2[b * NN + i0 + t];
    }
    __syncthreads();

    // p mapping: 4 threads/row, 16 j each
    int pi = t >> 2, jq = t & 3;
    float E1 = eS1[pi], E2 = eS2[pi];
    const int4* adj_row = reinterpret_cast<const int4*>(
                              adj + ((size_t)b * NN + i0 + pi) * NN) + jq * 4;
    const float4* sE4 = reinterpret_cast<const float4*>(sE);
    const float4* sG4 = reinterpret_cast<const float4*>(sG);
    float dreg = 0.f;

    // mma mapping
    int mbase = (w & 3) * 32, nbase = (w >> 2) * 64;
    int a_row = (l & 7) + ((l & 8) ? 8 : 0);
    int a_k = (l & 16) ? 16 : 0;
    int b_row = (l & 7) + ((l & 16) ? 8 : 0);
    int b_k = (l & 8) ? 16 : 0;

    const __half* hsrc = g_hTh + (size_t)b * FF * NN;

    const uint32_t PB[2] = {su + OFF_P0, su + OFF_P1};
    const uint32_t HB[2] = {su + OFF_H0, su + OFF_H1};

    #define AT_HFILL(jc, s)                                                  \
        do {                                                                 \
            _Pragma("unroll")                                                \
            for (int l2 = 0; l2 < 4; l2++) {                                 \
                int e = t + 512 * l2;                                        \
                int fr = e >> 3, sg = e & 7;                                 \
                cp16(HB[s] + fr * TSTRIDE + sg * 16,                         \
                     hsrc + (size_t)fr * NN + (jc) + sg * 8);                \
            }                                                                \
            CP_COMMIT();                                                     \
        } while (0)

    int4 aR[4];
    #pragma unroll
    for (int q = 0; q < 4; q++) aR[q] = adj_row[q];
    AT_HFILL(0, 0);

    float acc[2][8][4] = {};

    for (int c = 0; c < CHUNKS; c++) {
        int s = c & 1;
        int jc = c * 64;

        // ---- p(c) from prefetched adj regs ----
        {
            uint32_t pk[8];
            int jb = (jc >> 2) + jq * 4;
            #pragma unroll
            for (int q = 0; q < 4; q++) {
                int4 av = aR[q];
                float4 de = sE4[jb + q];
                float4 dg = sG4[jb + q];
                float u0 = E1 * de.x, u1 = E1 * de.y;
                float u2 = E1 * de.z, u3 = E1 * de.w;
                float p0 = u0 > 1.f ? u0 : E2 * dg.x;
                float p1 = u1 > 1.f ? u1 : E2 * dg.y;
                float p2 = u2 > 1.f ? u2 : E2 * dg.z;
                float p3 = u3 > 1.f ? u3 : E2 * dg.w;
                p0 = av.x ? p0 : 0.f;
                p1 = av.y ? p1 : 0.f;
                p2 = av.z ? p2 : 0.f;
                p3 = av.w ? p3 : 0.f;
                __half2 h0 = __floats2half2_rn(p0, p1);
                __half2 h1 = __floats2half2_rn(p2, p3);
                float2 f0 = __half22float2(h0);
                float2 f1 = __half22float2(h1);
                dreg += (f0.x + f0.y) + (f1.x + f1.y);
                pk[q * 2] = *reinterpret_cast<uint32_t*>(&h0);
                pk[q * 2 + 1] = *reinterpret_cast<uint32_t*>(&h1);
            }
            uint32_t pa = PB[s] + pi * TSTRIDE + jq * 32;
            asm volatile("st.shared.v4.b32 [%0], {%1,%2,%3,%4};" ::"r"(pa),
                         "r"(pk[0]), "r"(pk[1]), "r"(pk[2]), "r"(pk[3]) : "memory");
            asm volatile("st.shared.v4.b32 [%0], {%1,%2,%3,%4};" ::"r"(pa + 16),
                         "r"(pk[4]), "r"(pk[5]), "r"(pk[6]), "r"(pk[7]) : "memory");
        }
        // ---- prefetch adj(c+1), issue h(c+1) cp.async ----
        if (c + 1 < CHUNKS) {
            #pragma unroll
            for (int q = 0; q < 4; q++) aR[q] = adj_row[(c + 1) * 16 + q];
            AT_HFILL(jc + 64, s ^ 1);
            CP_WAIT1();
        } else {
            CP_WAIT0();
        }
        __syncthreads();

        // ---- f16 tensor-core GEMM on buffers s ----
        #pragma unroll
        for (int kk = 0; kk < 4; kk++) {
            uint32_t bf[4][4];
            #pragma unroll
            for (int g = 0; g < 4; g++)
                ldsm4(bf[g], HB[s] + (nbase + g * 16 + b_row) * TSTRIDE +
                                 kk * 32 + b_k);
            #pragma unroll
            for (int mt = 0; mt < 2; mt++) {
                uint32_t a[4];
                ldsm4(a, PB[s] + (mbase + mt * 16 + a_row) * TSTRIDE +
                             kk * 32 + a_k);
                #pragma unroll
                for (int g = 0; g < 4; g++) {
                    mma_f16(acc[mt][2 * g], a, bf[g][0], bf[g][1]);
                    mma_f16(acc[mt][2 * g + 1], a, bf[g][2], bf[g][3]);
                }
            }
        }
        __syncthreads();
    }

    // ---- denominators ----
    dreg += __shfl_xor_sync(0xFFFFFFFFu, dreg, 1);
    dreg += __shfl_xor_sync(0xFFFFFFFFu, dreg, 2);
    if ((t & 3) == 0) invd[pi] = (dreg > 0.f) ? (1.f / dreg) : 0.f;
    __syncthreads();

    // ---- epilogue ----
    #pragma unroll
    for (int mt = 0; mt < 2; mt++) {
        int lr = mbase + mt * 16 + (l >> 2);
        float s0 = invd[lr], s1v = invd[lr + 8];
        float* o0 = out + ((size_t)b * NN + i0 + lr) * FF + nbase;
        float* o1 = o0 + (size_t)8 * FF;
        #pragma unroll
        for (int nt = 0; nt < 8; nt++) {
            int cofs = nt * 8 + 2 * (l & 3);
            *reinterpret_cast<float2*>(o0 + cofs) =
                make_float2(acc[mt][nt][0] * s0, acc[mt][nt][1] * s0);
            *reinterpret_cast<float2*>(o1 + cofs) =
                make_float2(acc[mt][nt][2] * s1v, acc[mt][nt][3] * s1v);
        }
    }
}

// ---------------------------------------------------------------------------
extern "C" void kernel_launch(void* const* d_in, const int* in_sizes, int n_in,
                              void* d_out, int out_size) {
    const float* x     = (const float*)d_in[0];  // (B,N,F_in)
    const int*   adj   = (const int*)d_in[1];    // (B,N,N)
    const float* W     = (const float*)d_in[2];  // (F_out,F_in)
    const float* a_src = (const float*)d_in[3];  // (F_out)
    const float* a_dst = (const float*)d_in[4];  // (F_out)
    float* out = (float*)d_out;                  // (B,N,F_out)

    (void)in_sizes; (void)n_in; (void)out_size;

    // convert x, W to f16 (kernels write the device globals directly)
    cvt_x_kernel<<<BB * NN * FF / 4 / 256, 256>>>((const float4*)x);
    cvt_w_kernel<<<FF * FF / 4 / 256, 256>>>((const float4*)W);

    // h_T = W @ x^T (f16 tensor cores)
    cudaFuncSetAttribute(gemm_h_kernel, cudaFuncAttributeMaxDynamicSharedMemorySize,
                         GH_SMEM);
    gemm_h_kernel<<<dim3(NN / 128, FF / 128, BB), 256, GH_SMEM>>>();

    // scores -> exp factors
    score_kernel<<<(BB * NN) / 256, 256>>>(a_src, a_dst);

    // fused masked softmax + alpha @ h
    cudaFuncSetAttribute(attn_kernel, cudaFuncAttributeMaxDynamicSharedMemorySize,
                         AT_SMEM);
    attn_kernel<<<dim3(NN / ITILE, BB), 512, AT_SMEM>>>(adj, out);
}